// round 5
// baseline (speedup 1.0000x reference)
#include <cuda_runtime.h>
#include <cstdint>

// NoReFT on [B,768] fp32, regions start {0,752,184,568}, width 16.
// Full TMA pipeline: bulk G->S load, in-smem fixup of 64 channels/row,
// bulk S->G store. 4-stage ring of 24KB tiles (8 rows each).

#define T_ROWS 8
#define TILE_F (T_ROWS * 768)            // 6144 floats
#define TILE_BYTES (TILE_F * 4)          // 24576 B
#define STAGES 4
#define NT 512
#define GRID 304                         // 2 per SM on 152 SMs

// smem float offsets
#define SM_M   (STAGES * TILE_F)                 // after ring: 24576 floats
#define SM_C   (SM_M + 4 * 16 * 16)
#define SM_BAR (SM_C + 64)                       // 8B-aligned (even float idx)
#define SM_BYTES (SM_BAR * 4 + STAGES * 8)

__device__ __forceinline__ void mbar_init(uint32_t a, uint32_t cnt) {
    asm volatile("mbarrier.init.shared.b64 [%0], %1;" :: "r"(a), "r"(cnt) : "memory");
}
__device__ __forceinline__ void mbar_expect_tx(uint32_t a, uint32_t bytes) {
    asm volatile("mbarrier.arrive.expect_tx.shared.b64 _, [%0], %1;" :: "r"(a), "r"(bytes) : "memory");
}
__device__ __forceinline__ void mbar_wait(uint32_t a, uint32_t parity) {
    asm volatile(
        "{\n\t.reg .pred P;\n\t"
        "LW_%=:\n\t"
        "mbarrier.try_wait.parity.acquire.cta.shared::cta.b64 P, [%0], %1, 0x989680;\n\t"
        "@P bra LD_%=;\n\t"
        "bra LW_%=;\n\t"
        "LD_%=:\n\t}"
        :: "r"(a), "r"(parity) : "memory");
}
__device__ __forceinline__ void bulk_ld(uint32_t dst, const void* src, uint32_t bytes, uint32_t bar) {
    asm volatile("cp.async.bulk.shared::cta.global.mbarrier::complete_tx::bytes [%0], [%1], %2, [%3];"
                 :: "r"(dst), "l"(src), "r"(bytes), "r"(bar) : "memory");
}
__device__ __forceinline__ void bulk_st(void* dst, uint32_t src, uint32_t bytes) {
    asm volatile("cp.async.bulk.global.shared::cta.bulk_group [%0], [%1], %2;"
                 :: "l"(dst), "r"(src), "r"(bytes) : "memory");
}
__device__ __forceinline__ void bulk_commit() {
    asm volatile("cp.async.bulk.commit_group;" ::: "memory");
}
__device__ __forceinline__ void bulk_wait_read0() {
    asm volatile("cp.async.bulk.wait_group.read 0;" ::: "memory");
}
__device__ __forceinline__ void fence_async() {
    asm volatile("fence.proxy.async.shared::cta;" ::: "memory");
}

__device__ __forceinline__ int start_of(int g) {
    return g == 0 ? 0 : g == 1 ? 752 : g == 2 ? 184 : 568;
}

__global__ __launch_bounds__(NT) void minireft_tma2(
    const float* __restrict__ base, float* __restrict__ out,
    const float* __restrict__ Wp, const float* __restrict__ bp,
    const float* __restrict__ Ws, const float* __restrict__ bs,
    int B, int nTiles)
{
    extern __shared__ float smem[];
    float* sM = smem + SM_M;   // [4][16][16]: sM[(g*16+e)*16+l]
    float* sC = smem + SM_C;   // [4][16]
    const uint32_t smem_u32 = (uint32_t)__cvta_generic_to_shared(smem);
    const uint32_t bar0 = smem_u32 + SM_BAR * 4;

    const int tid = threadIdx.x;

    // ---- fold weights ----
    for (int idx = tid; idx < 4 * 16 * 16; idx += NT) {
        int g = idx >> 8, e = (idx >> 4) & 15, l = idx & 15;
        float acc = 0.f;
        #pragma unroll
        for (int r = 0; r < 8; r++) {
            float wp = Wp[g * 128 + r * 16 + e];
            float ws = Ws[g * 128 + r * 16 + e];
            acc += (ws - wp) * Wp[g * 128 + r * 16 + l];
        }
        sM[idx] = acc;
    }
    for (int idx = tid; idx < 4 * 16; idx += NT) {
        int g = idx >> 4, l = idx & 15;
        float acc = 0.f;
        #pragma unroll
        for (int r = 0; r < 8; r++)
            acc += (bs[g * 8 + r] - bp[g * 8 + r]) * Wp[g * 128 + r * 16 + l];
        sC[idx] = acc;
    }
    if (tid < STAGES) mbar_init(bar0 + tid * 8, 1);
    __syncthreads();
    if (tid == 0) fence_async();
    __syncthreads();

    // ---- remainder rows (B % T_ROWS) via plain LDG path on block 0 ----
    if (blockIdx.x == 0 && (B & (T_ROWS - 1))) {
        const long long remStart = (long long)nTiles * T_ROWS;
        for (long long row = remStart; row < B; row++) {
            // copy the full row, then patch regions (512 threads, 768 floats)
            for (int c = tid; c < 768; c += NT)
                out[row * 768 + c] = base[row * 768 + c];
            __syncthreads();
            if (tid < 64) {
                int g = tid >> 4, l = tid & 15;
                int st = start_of(g);
                float d = sC[g * 16 + l];
                #pragma unroll
                for (int e = 0; e < 16; e++)
                    d += sM[(g * 16 + e) * 16 + l] * base[row * 768 + st + e];
                out[row * 768 + st + l] = base[row * 768 + st + l] + d;
            }
            __syncthreads();
        }
    }

    // ---- fixup geometry for this thread (one of 512 edited floats/tile) ----
    const int frow = tid >> 6;          // 0..7 (tile row)
    const int g    = (tid >> 4) & 3;    // region
    const int l    = tid & 15;          // channel within region
    const int xoff = frow * 768 + start_of(g);

    // ---- persistent tile loop ----
    const int bid = blockIdx.x;
    int count = 0;
    if (bid < nTiles) count = (nTiles - bid + GRID - 1) / GRID;

    if (tid == 0) {
        int pre = count < STAGES ? count : STAGES;
        for (int k = 0; k < pre; k++) {
            long long tile = (long long)bid + (long long)k * GRID;
            mbar_expect_tx(bar0 + k * 8, TILE_BYTES);
            bulk_ld(smem_u32 + (uint32_t)(k * TILE_BYTES),
                    base + tile * TILE_F, TILE_BYTES, bar0 + k * 8);
        }
    }

    for (int k = 0; k < count; k++) {
        const int s = k - (k / STAGES) * STAGES;
        const int parity = (k / STAGES) & 1;
        mbar_wait(bar0 + s * 8, parity);

        float* sb = smem + s * TILE_F;

        // patch 16 channels of region g in row frow (in place)
        {
            float x[16];
            #pragma unroll
            for (int e = 0; e < 16; e++) x[e] = sb[xoff + e];
            float d = sC[g * 16 + l];
            #pragma unroll
            for (int e = 0; e < 16; e++)
                d += sM[(g * 16 + e) * 16 + l] * x[e];
            sb[xoff + l] = x[l] + d;
        }
        __syncthreads();

        const long long tile = (long long)bid + (long long)k * GRID;
        if (tid == 0) {
            fence_async();
            bulk_st(out + tile * TILE_F, smem_u32 + (uint32_t)(s * TILE_BYTES), TILE_BYTES);
            bulk_commit();
            if (k + STAGES < count) {
                bulk_wait_read0();   // TMA done READING this stage's smem
                long long nt = (long long)bid + (long long)(k + STAGES) * GRID;
                mbar_expect_tx(bar0 + s * 8, TILE_BYTES);
                bulk_ld(smem_u32 + (uint32_t)(s * TILE_BYTES),
                        base + nt * TILE_F, TILE_BYTES, bar0 + s * 8);
            }
        }
    }
}

extern "C" void kernel_launch(void* const* d_in, const int* in_sizes, int n_in,
                              void* d_out, int out_size)
{
    const float* base = (const float*)d_in[0];  // [1, B, 768]
    const float* Wp   = (const float*)d_in[1];
    const float* bp   = (const float*)d_in[2];
    const float* Ws   = (const float*)d_in[3];
    const float* bs   = (const float*)d_in[4];
    float* out = (float*)d_out;

    const int B = in_sizes[0] / 768;
    const int nTiles = B / T_ROWS;

    static int configured = 0;
    if (!configured) {
        cudaFuncSetAttribute(minireft_tma2,
                             cudaFuncAttributeMaxDynamicSharedMemorySize, SM_BYTES);
        configured = 1;
    }

    minireft_tma2<<<GRID, NT, SM_BYTES>>>(base, out, Wp, bp, Ws, bs, B, nTiles);
}

// round 6
// speedup vs baseline: 1.0346x; 1.0346x over previous
#include <cuda_runtime.h>
#include <cstdint>

// NoReFT on [B,768] fp32, regions start {0,752,184,568}, width 16.
// Full TMA pipeline: bulk G->S load, in-smem fixup of 64 channels/row,
// bulk S->G store. 4-stage ring of 24KB tiles (8 rows), DELAY=2 reuse slack
// so loads never wait on the just-committed store.

#define T_ROWS 8
#define TILE_F (T_ROWS * 768)            // 6144 floats
#define TILE_BYTES (TILE_F * 4)          // 24576 B
#define STAGES 4
#define DELAY 2
#define NT 512
#define GRID 304                         // 2 per SM on 152 SMs

// smem float offsets
#define SM_M   (STAGES * TILE_F)
#define SM_C   (SM_M + 4 * 16 * 16)
#define SM_BAR (SM_C + 64)               // even float index -> 8B aligned
#define SM_BYTES (SM_BAR * 4 + STAGES * 8)

__device__ __forceinline__ void mbar_init(uint32_t a, uint32_t cnt) {
    asm volatile("mbarrier.init.shared.b64 [%0], %1;" :: "r"(a), "r"(cnt) : "memory");
}
__device__ __forceinline__ void mbar_expect_tx(uint32_t a, uint32_t bytes) {
    asm volatile("mbarrier.arrive.expect_tx.shared.b64 _, [%0], %1;" :: "r"(a), "r"(bytes) : "memory");
}
__device__ __forceinline__ void mbar_wait(uint32_t a, uint32_t parity) {
    asm volatile(
        "{\n\t.reg .pred P;\n\t"
        "LW_%=:\n\t"
        "mbarrier.try_wait.parity.acquire.cta.shared::cta.b64 P, [%0], %1, 0x989680;\n\t"
        "@P bra LD_%=;\n\t"
        "bra LW_%=;\n\t"
        "LD_%=:\n\t}"
        :: "r"(a), "r"(parity) : "memory");
}
__device__ __forceinline__ void bulk_ld(uint32_t dst, const void* src, uint32_t bytes, uint32_t bar) {
    asm volatile("cp.async.bulk.shared::cta.global.mbarrier::complete_tx::bytes [%0], [%1], %2, [%3];"
                 :: "r"(dst), "l"(src), "r"(bytes), "r"(bar) : "memory");
}
__device__ __forceinline__ void bulk_st(void* dst, uint32_t src, uint32_t bytes) {
    asm volatile("cp.async.bulk.global.shared::cta.bulk_group [%0], [%1], %2;"
                 :: "l"(dst), "r"(src), "r"(bytes) : "memory");
}
__device__ __forceinline__ void bulk_commit() {
    asm volatile("cp.async.bulk.commit_group;" ::: "memory");
}
template<int N>
__device__ __forceinline__ void bulk_wait_read() {
    asm volatile("cp.async.bulk.wait_group.read %0;" :: "n"(N) : "memory");
}
__device__ __forceinline__ void fence_async() {
    asm volatile("fence.proxy.async.shared::cta;" ::: "memory");
}

__device__ __forceinline__ int start_of(int g) {
    return g == 0 ? 0 : g == 1 ? 752 : g == 2 ? 184 : 568;
}

__global__ __launch_bounds__(NT) void minireft_tma3(
    const float* __restrict__ base, float* __restrict__ out,
    const float* __restrict__ Wp, const float* __restrict__ bp,
    const float* __restrict__ Ws, const float* __restrict__ bs,
    int B, int nTiles)
{
    extern __shared__ float smem[];
    float* sM = smem + SM_M;   // [4][16][16]: sM[(g*16+e)*16+l]
    float* sC = smem + SM_C;   // [4][16]
    const uint32_t smem_u32 = (uint32_t)__cvta_generic_to_shared(smem);
    const uint32_t bar0 = smem_u32 + SM_BAR * 4;

    const int tid = threadIdx.x;

    // ---- fold weights ----
    for (int idx = tid; idx < 4 * 16 * 16; idx += NT) {
        int g = idx >> 8, e = (idx >> 4) & 15, l = idx & 15;
        float acc = 0.f;
        #pragma unroll
        for (int r = 0; r < 8; r++) {
            float wp = Wp[g * 128 + r * 16 + e];
            float ws = Ws[g * 128 + r * 16 + e];
            acc += (ws - wp) * Wp[g * 128 + r * 16 + l];
        }
        sM[idx] = acc;
    }
    for (int idx = tid; idx < 4 * 16; idx += NT) {
        int g = idx >> 4, l = idx & 15;
        float acc = 0.f;
        #pragma unroll
        for (int r = 0; r < 8; r++)
            acc += (bs[g * 8 + r] - bp[g * 8 + r]) * Wp[g * 128 + r * 16 + l];
        sC[idx] = acc;
    }
    if (tid < STAGES) mbar_init(bar0 + tid * 8, 1);
    __syncthreads();
    if (tid == 0) fence_async();
    __syncthreads();

    // ---- remainder rows (B % T_ROWS) on block 0 ----
    if (blockIdx.x == 0 && (B & (T_ROWS - 1))) {
        const long long remStart = (long long)nTiles * T_ROWS;
        for (long long row = remStart; row < B; row++) {
            for (int c = tid; c < 768; c += NT)
                out[row * 768 + c] = base[row * 768 + c];
            __syncthreads();
            if (tid < 64) {
                int g = tid >> 4, l = tid & 15;
                int st = start_of(g);
                float d = sC[g * 16 + l];
                #pragma unroll
                for (int e = 0; e < 16; e++)
                    d += sM[(g * 16 + e) * 16 + l] * base[row * 768 + st + e];
                out[row * 768 + st + l] = base[row * 768 + st + l] + d;
            }
            __syncthreads();
        }
    }

    // ---- fixup geometry: one edited float per thread per tile ----
    const int frow = tid >> 6;          // tile row 0..7
    const int g    = (tid >> 4) & 3;    // region
    const int l    = tid & 15;          // channel in region
    const int xoff = frow * 768 + start_of(g);

    const int bid = blockIdx.x;
    int count = 0;
    if (bid < nTiles) count = (nTiles - bid + GRID - 1) / GRID;

    // prologue: fill all stages
    if (tid == 0) {
        int pre = count < STAGES ? count : STAGES;
        for (int k = 0; k < pre; k++) {
            long long tile = (long long)bid + (long long)k * GRID;
            mbar_expect_tx(bar0 + k * 8, TILE_BYTES);
            bulk_ld(smem_u32 + (uint32_t)(k * TILE_BYTES),
                    base + tile * TILE_F, TILE_BYTES, bar0 + k * 8);
        }
    }

    for (int k = 0; k < count; k++) {
        const int s = k & (STAGES - 1);
        mbar_wait(bar0 + s * 8, (k >> 2) & 1);

        float* sb = smem + s * TILE_F;

        // in-place patch: 16 channels of region g in row frow
        {
            float x[16];
            #pragma unroll
            for (int e = 0; e < 16; e++) x[e] = sb[xoff + e];
            float d = sC[g * 16 + l];
            #pragma unroll
            for (int e = 0; e < 16; e++)
                d += sM[(g * 16 + e) * 16 + l] * x[e];
            sb[xoff + l] = x[l] + d;
        }
        fence_async();
        __syncthreads();

        if (tid == 0) {
            const long long tile = (long long)bid + (long long)k * GRID;
            bulk_st(out + tile * TILE_F,
                    smem_u32 + (uint32_t)(s * TILE_BYTES), TILE_BYTES);
            bulk_commit();

            // Reload the buffer stored DELAY iterations ago: its smem read is
            // guaranteed complete once <= DELAY newer groups remain pending.
            const int j = k - DELAY;
            if (j >= 0 && j + STAGES < count) {
                bulk_wait_read<DELAY>();
                const int sj = j & (STAGES - 1);
                long long nt = (long long)bid + (long long)(j + STAGES) * GRID;
                mbar_expect_tx(bar0 + sj * 8, TILE_BYTES);
                bulk_ld(smem_u32 + (uint32_t)(sj * TILE_BYTES),
                        base + nt * TILE_F, TILE_BYTES, bar0 + sj * 8);
            }
        }
    }
}

extern "C" void kernel_launch(void* const* d_in, const int* in_sizes, int n_in,
                              void* d_out, int out_size)
{
    const float* base = (const float*)d_in[0];  // [1, B, 768]
    const float* Wp   = (const float*)d_in[1];
    const float* bp   = (const float*)d_in[2];
    const float* Ws   = (const float*)d_in[3];
    const float* bs   = (const float*)d_in[4];
    float* out = (float*)d_out;

    const int B = in_sizes[0] / 768;
    const int nTiles = B / T_ROWS;

    static int configured = 0;
    if (!configured) {
        cudaFuncSetAttribute(minireft_tma3,
                             cudaFuncAttributeMaxDynamicSharedMemorySize, SM_BYTES);
        configured = 1;
    }

    minireft_tma3<<<GRID, NT, SM_BYTES>>>(base, out, Wp, bp, Ws, bs, B, nTiles);
}

// round 7
// speedup vs baseline: 1.2359x; 1.1946x over previous
#include <cuda_runtime.h>
#include <cstdint>

// NoReFT on [B,768] fp32, regions start {0,752,184,568}, width 16.
// TMA G->S load pipeline (4 stages x 12KB = 4 rows), register consume with
// region fixup, STG.128 .cs stores. 4 CTAs/SM.

#define T_ROWS 4
#define TILE_F (T_ROWS * 768)            // 3072 floats
#define TILE_F4 (TILE_F / 4)             // 768
#define TILE_BYTES (TILE_F * 4)          // 12288 B
#define STAGES 4
#define NT 256
#define MAXGRID 2048

// smem float offsets
#define SM_M   (STAGES * TILE_F)                 // 12288
#define SM_C   (SM_M + 4 * 16 * 16)
#define SM_BAR (SM_C + 64)                       // even -> 8B aligned
#define SM_BYTES (SM_BAR * 4 + STAGES * 8)

__device__ __forceinline__ void mbar_init(uint32_t a, uint32_t cnt) {
    asm volatile("mbarrier.init.shared.b64 [%0], %1;" :: "r"(a), "r"(cnt) : "memory");
}
__device__ __forceinline__ void mbar_expect_tx(uint32_t a, uint32_t bytes) {
    asm volatile("mbarrier.arrive.expect_tx.shared.b64 _, [%0], %1;" :: "r"(a), "r"(bytes) : "memory");
}
__device__ __forceinline__ void mbar_wait(uint32_t a, uint32_t parity) {
    asm volatile(
        "{\n\t.reg .pred P;\n\t"
        "LW_%=:\n\t"
        "mbarrier.try_wait.parity.acquire.cta.shared::cta.b64 P, [%0], %1, 0x989680;\n\t"
        "@P bra LD_%=;\n\t"
        "bra LW_%=;\n\t"
        "LD_%=:\n\t}"
        :: "r"(a), "r"(parity) : "memory");
}
__device__ __forceinline__ void bulk_ld(uint32_t dst, const void* src, uint32_t bytes, uint32_t bar) {
    asm volatile("cp.async.bulk.shared::cta.global.mbarrier::complete_tx::bytes [%0], [%1], %2, [%3];"
                 :: "r"(dst), "l"(src), "r"(bytes), "r"(bar) : "memory");
}

__device__ __forceinline__ int region_of(int c4, int& off) {
    if (c4 < 4)                 { off = c4;       return 0; }
    if (c4 >= 188)              { off = c4 - 188; return 1; }
    if (c4 >= 46 && c4 < 50)    { off = c4 - 46;  return 2; }
    if (c4 >= 142 && c4 < 146)  { off = c4 - 142; return 3; }
    off = 0; return -1;
}
__device__ __forceinline__ int start4_of(int g) {
    return g == 0 ? 0 : g == 1 ? 188 : g == 2 ? 46 : 142;
}
__device__ __forceinline__ int start_of(int g) {
    return g == 0 ? 0 : g == 1 ? 752 : g == 2 ? 184 : 568;
}

__global__ __launch_bounds__(NT) void minireft_v7(
    const float* __restrict__ base, float* __restrict__ out,
    const float* __restrict__ Wp, const float* __restrict__ bp,
    const float* __restrict__ Ws, const float* __restrict__ bs,
    int B, int nTiles, int grid)
{
    extern __shared__ float smem[];
    float* sM = smem + SM_M;   // [4][16][16]: sM[(g*16+e)*16+l]
    float* sC = smem + SM_C;   // [4][16]
    const uint32_t smem_u32 = (uint32_t)__cvta_generic_to_shared(smem);
    const uint32_t bar0 = smem_u32 + SM_BAR * 4;

    const int tid = threadIdx.x;

    // ---- fold weights ----
    for (int idx = tid; idx < 4 * 16 * 16; idx += NT) {
        int g = idx >> 8, e = (idx >> 4) & 15, l = idx & 15;
        float acc = 0.f;
        #pragma unroll
        for (int r = 0; r < 8; r++) {
            float wp = Wp[g * 128 + r * 16 + e];
            float ws = Ws[g * 128 + r * 16 + e];
            acc += (ws - wp) * Wp[g * 128 + r * 16 + l];
        }
        sM[idx] = acc;
    }
    for (int idx = tid; idx < 4 * 16; idx += NT) {
        int g = idx >> 4, l = idx & 15;
        float acc = 0.f;
        #pragma unroll
        for (int r = 0; r < 8; r++)
            acc += (bs[g * 8 + r] - bp[g * 8 + r]) * Wp[g * 128 + r * 16 + l];
        sC[idx] = acc;
    }
    if (tid < STAGES) mbar_init(bar0 + tid * 8, 1);
    __syncthreads();

    // ---- remainder rows (B % T_ROWS) on block 0 (plain path) ----
    if (blockIdx.x == 0 && (B & (T_ROWS - 1))) {
        const long long remStart = (long long)nTiles * T_ROWS;
        for (long long row = remStart; row < B; row++) {
            for (int c = tid; c < 768; c += NT)
                out[row * 768 + c] = base[row * 768 + c];
            __syncthreads();
            if (tid < 64) {
                int g = tid >> 4, l = tid & 15;
                int st = start_of(g);
                float d = sC[g * 16 + l];
                #pragma unroll
                for (int e = 0; e < 16; e++)
                    d += sM[(g * 16 + e) * 16 + l] * base[row * 768 + st + e];
                out[row * 768 + st + l] = base[row * 768 + st + l] + d;
            }
            __syncthreads();
        }
    }

    // ---- per-thread geometry: 3 chunks per thread ----
    int rowb_[3], g_[3], q_[3];
    #pragma unroll
    for (int j = 0; j < 3; j++) {
        int chunk = tid + NT * j;          // 0..767
        int row = chunk / 192;
        int c4 = chunk - row * 192;
        rowb_[j] = row * 768;              // float offset of row in tile
        int off; g_[j] = region_of(c4, off); q_[j] = off * 4;
    }

    const int bid = blockIdx.x;
    int count = 0;
    if (bid < nTiles) count = (nTiles - bid + grid - 1) / grid;

    // prologue: fill pipeline
    if (tid == 0) {
        int pre = count < STAGES ? count : STAGES;
        for (int k = 0; k < pre; k++) {
            long long tile = (long long)bid + (long long)k * grid;
            mbar_expect_tx(bar0 + k * 8, TILE_BYTES);
            bulk_ld(smem_u32 + (uint32_t)(k * TILE_BYTES),
                    base + tile * TILE_F, TILE_BYTES, bar0 + k * 8);
        }
    }

    for (int k = 0; k < count; k++) {
        const int s = k & (STAGES - 1);
        mbar_wait(bar0 + s * 8, (k >> 2) & 1);

        const float* sb = smem + s * TILE_F;
        const float4* sb4 = (const float4*)sb;
        const long long tile = (long long)bid + (long long)k * grid;
        float4* op = (float4*)out + tile * TILE_F4;

        #pragma unroll
        for (int j = 0; j < 3; j++) {
            const int chunk = tid + NT * j;
            float4 v = sb4[chunk];
            const int g = g_[j];
            if (g >= 0) {
                const float* xb = sb + rowb_[j] + start_of(g);
                const int q = q_[j];
                float d0 = sC[g*16+q], d1 = sC[g*16+q+1],
                      d2 = sC[g*16+q+2], d3 = sC[g*16+q+3];
                #pragma unroll
                for (int e = 0; e < 16; e++) {
                    float xe = xb[e];
                    d0 += sM[(g*16+e)*16+q  ] * xe;
                    d1 += sM[(g*16+e)*16+q+1] * xe;
                    d2 += sM[(g*16+e)*16+q+2] * xe;
                    d3 += sM[(g*16+e)*16+q+3] * xe;
                }
                v.x += d0; v.y += d1; v.z += d2; v.w += d3;
            }
            __stcs(op + chunk, v);
        }

        __syncthreads();   // everyone done reading stage s

        if (tid == 0 && k + STAGES < count) {
            long long nt = (long long)bid + (long long)(k + STAGES) * grid;
            mbar_expect_tx(bar0 + s * 8, TILE_BYTES);
            bulk_ld(smem_u32 + (uint32_t)(s * TILE_BYTES),
                    base + nt * TILE_F, TILE_BYTES, bar0 + s * 8);
        }
    }
}

extern "C" void kernel_launch(void* const* d_in, const int* in_sizes, int n_in,
                              void* d_out, int out_size)
{
    const float* base = (const float*)d_in[0];  // [1, B, 768]
    const float* Wp   = (const float*)d_in[1];
    const float* bp   = (const float*)d_in[2];
    const float* Ws   = (const float*)d_in[3];
    const float* bs   = (const float*)d_in[4];
    float* out = (float*)d_out;

    const int B = in_sizes[0] / 768;
    const int nTiles = B / T_ROWS;

    int grid = nTiles < MAXGRID ? (nTiles > 0 ? nTiles : 1) : MAXGRID;

    static int configured = 0;
    if (!configured) {
        cudaFuncSetAttribute(minireft_v7,
                             cudaFuncAttributeMaxDynamicSharedMemorySize, SM_BYTES);
        configured = 1;
    }

    minireft_v7<<<grid, NT, SM_BYTES>>>(base, out, Wp, bp, Ws, bs, B, nTiles, grid);
}